// round 14
// baseline (speedup 1.0000x reference)
#include <cuda_runtime.h>
#include <cuda_fp16.h>
#include <math.h>
#include <stdint.h>

#define BB   2
#define SS   2048
#define EE   8
#define LL   2056
#define HIDD 768
#define HDD  64
#define NHH  12
#define MTOT (BB*LL)         // 4112
#define MPAD 4224            // 33 * 128
#define NKV  (2*HIDD)
#define NT   17
#define MW   68
#define NKC  24              // k-chunks of 32
#define NMB  33              // m-blocks of 128
#define NNB  12              // n-blocks of 128
#define NBH  (BB*NHH)

// ---------------- scratch (tiled, pre-swizzled layouts) ----------------
__device__ __align__(16) __half g_Qf[NBH*SS*HDD];                // [bh][s][d], scaled by 0.125*log2(e)
__device__ __align__(16) __half g_Eh2[NKC*NMB*4096];             // per (kc,mblk): 128r x 4u tile
__device__ __align__(16) __half g_El2[NKC*NMB*4096];
__device__ __align__(16) __half g_Wh2[NKC*NNB*4096];
__device__ __align__(16) __half g_Wl2[NKC*NNB*4096];
__device__ __align__(16) __half g_Kt [NBH*NT*8192];              // per (bh,kt): 128r x 8u tile
__device__ __align__(16) __half g_Vtt[NBH*NT*8192];              // per (bh,kt): 64d x 16u tile
__device__ __align__(16) unsigned g_mask[BB*SS*MW];
__device__ float g_emb[LL*HDD];

// ---------------- swizzled unit positions (unit = 16B = 8 halfs) ----------------
__device__ __forceinline__ int pA(int r, int s) {
    int q = r >> 1, j = s + ((r & 1) << 2);
    return q * 8 + (j ^ (q & 7));
}
__device__ __forceinline__ int pK(int r, int s) { return r * 8 + (s ^ (r & 7)); }
__device__ __forceinline__ int pV(int d, int s) { return d * 16 + (s ^ (d & 7)); }

// ---------------- helpers ----------------
__device__ __forceinline__ uint32_t smem_u32(const void* p) {
    uint32_t a;
    asm("{ .reg .u64 t; cvta.to.shared.u64 t, %1; cvt.u32.u64 %0, t; }" : "=r"(a) : "l"(p));
    return a;
}
__device__ __forceinline__ uint32_t packh2(float lo, float hi) {
    uint32_t r; asm("cvt.rn.f16x2.f32 %0, %1, %2;" : "=r"(r) : "f"(hi), "f"(lo)); return r;
}
__device__ __forceinline__ void mma16816(float* c, const uint32_t* a, uint32_t b0, uint32_t b1) {
    asm volatile("mma.sync.aligned.m16n8k16.row.col.f32.f16.f16.f32 "
        "{%0,%1,%2,%3}, {%4,%5,%6,%7}, {%8,%9}, {%0,%1,%2,%3};"
        : "+f"(c[0]), "+f"(c[1]), "+f"(c[2]), "+f"(c[3])
        : "r"(a[0]), "r"(a[1]), "r"(a[2]), "r"(a[3]), "r"(b0), "r"(b1));
}
__device__ __forceinline__ void ldmx4(uint32_t a, uint32_t* r) {
    asm volatile("ldmatrix.sync.aligned.m8n8.x4.shared.b16 {%0,%1,%2,%3}, [%4];"
        : "=r"(r[0]), "=r"(r[1]), "=r"(r[2]), "=r"(r[3]) : "r"(a));
}
__device__ __forceinline__ void bulkcp(uint32_t dst, const void* src, uint32_t bytes, uint32_t mbar) {
    asm volatile("cp.async.bulk.shared::cluster.global.mbarrier::complete_tx::bytes [%0], [%1], %2, [%3];"
        :: "r"(dst), "l"(src), "r"(bytes), "r"(mbar) : "memory");
}
#define MBAR_INIT(a, c) \
    asm volatile("mbarrier.init.shared.b64 [%0], %1;" :: "r"(a), "r"((uint32_t)(c)) : "memory")
#define MBAR_EXPECT(a, tx) \
    asm volatile("mbarrier.arrive.expect_tx.shared.b64 _, [%0], %1;" :: "r"(a), "r"((uint32_t)(tx)) : "memory")
#define MBAR_WAIT(a, ph) do { \
    uint32_t _m = (a), _p = (uint32_t)(ph), _d; \
    asm volatile("{\n\t.reg .pred p;\n\tmbarrier.try_wait.parity.acquire.cta.shared::cta.b64 p, [%1], %2;\n\tselp.b32 %0, 1, 0, p;\n\t}" \
        : "=r"(_d) : "r"(_m), "r"(_p) : "memory"); \
    if (!_d) { \
        asm volatile("{\n\t.reg .pred P1;\n\tWL_%=:\n\tmbarrier.try_wait.parity.acquire.cta.shared::cta.b64 P1, [%0], %1, 0x989680;\n\t@P1 bra.uni WD_%=;\n\tbra.uni WL_%=;\n\tWD_%=:\n\t}" \
            :: "r"(_m), "r"(_p) : "memory"); \
    } \
} while (0)

// ---------------- kernel 0: sinusoidal table ----------------
__global__ void emb_kernel() {
    int idx = blockIdx.x * blockDim.x + threadIdx.x;
    if (idx >= LL * 32) return;
    int p = idx >> 5, j = idx & 31;
    float divf = (float)exp(-(double)(2 * j) * (9.210340371976184 / 64.0));
    float angf = (float)p * divf;
    double ang = (double)angf;
    g_emb[p * 64 + 2 * j]     = (float)sin(ang);
    g_emb[p * 64 + 2 * j + 1] = (float)cos(ang);
}

// ---------------- kernel 1: Q rope + (0.125*log2e) scale -> fp16 ----------------
#define QSCALE 0.1803368801111204f   // 0.125 * log2(e)
__global__ void qf16_kernel(const float* __restrict__ qh) {
    int idx = blockIdx.x * blockDim.x + threadIdx.x;
    if (idx >= BB * SS * NHH * 32) return;
    int i = idx & 31;
    int t = idx >> 5;
    int h = t % NHH;  t /= NHH;
    int p = t % SS;
    int b = t / SS;
    const float2 x = *(const float2*)(qh + ((size_t)(b * SS + p)) * HIDD + h * HDD + 2 * i);
    float si = g_emb[p * 64 + i];
    float ci = g_emb[p * 64 + 32 + i];
    size_t o = ((size_t)(b * NHH + h) * SS + p) * HDD + 2 * i;
    *(uint32_t*)(&g_Qf[o]) = packh2(-x.y * ci * QSCALE, x.x * si * QSCALE);
}

// ---------------- fused prep: packmask + zeropad + esplit + wsplit ----------------
#define PM_BLK 512
#define ZP_BLK 180
#define ES_BLK 3168
#define WS_BLK 1152
#define PREP_GRID (PM_BLK + ZP_BLK + ES_BLK + WS_BLK)

__device__ __forceinline__ void split2(float a, float b, uint32_t& hw, uint32_t& lw) {
    __half ha = __float2half_rn(a), hb = __float2half_rn(b);
    hw = ((uint32_t)__half_as_ushort(hb) << 16) | __half_as_ushort(ha);
    __half la = __float2half_rn(a - __half2float(ha));
    __half lb = __float2half_rn(b - __half2float(hb));
    lw = ((uint32_t)__half_as_ushort(lb) << 16) | __half_as_ushort(la);
}

__global__ void prep_kernel(const float* __restrict__ rnd, const float* __restrict__ kvh,
                            const float* __restrict__ embx, const float* __restrict__ W) {
    const int bid = blockIdx.x, tid = threadIdx.x;
    if (bid < PM_BLK) {
        int wid_g = bid * 8 + (tid >> 5);
        int lane = tid & 31;
        int b = wid_g >> 11, q = wid_g & 2047;
        const float* rrow = rnd + ((size_t)(b * SS + q)) * SS;
        unsigned* mrow = g_mask + (size_t)wid_g * MW;
        for (int w = 0; w < MW; ++w) {
            int j = w * 32 + lane;
            bool ok;
            if (j < EE) ok = true;
            else {
                int jj = j - EE;
                ok = (jj < SS) ? ((rrow[jj] >= 0.1f) & (jj != q)) : false;
            }
            unsigned bal = __ballot_sync(0xffffffffu, ok);
            if (lane == 0) mrow[w] = bal;
        }
    } else if (bid < PM_BLK + ZP_BLK) {
        int idx = (bid - PM_BLK) * 256 + tid;   // 0 .. 46079
        const uint4 z = make_uint4(0, 0, 0, 0);
        if (idx < 23040) {                       // K pad: tile kt=16, rows 8..127
            int s = idx & 7;
            int t2 = idx >> 3;
            int r = 8 + t2 % 120;
            int bh = t2 / 120;
            *(uint4*)(&g_Kt[((size_t)(bh * NT + 16)) * 8192 + pK(r, s) * 8]) = z;
        } else {                                 // V pad: tile kt=16, units 1..15
            int i2 = idx - 23040;
            int s = 1 + i2 % 15;
            int t2 = i2 / 15;
            int d = t2 & 63;
            int bh = t2 >> 6;
            *(uint4*)(&g_Vtt[((size_t)(bh * NT + 16)) * 8192 + pV(d, s) * 8]) = z;
        }
    } else if (bid < PM_BLK + ZP_BLK + ES_BLK) {
        int idx = (bid - PM_BLK - ZP_BLK) * 256 + tid;
        int m = idx / 192, c4 = (idx % 192) * 4;
        float4 v = make_float4(0.f, 0.f, 0.f, 0.f);
        if (m < MTOT) {
            int b = m / LL, l = m % LL;
            const float* row = (l < EE) ? (embx + ((size_t)b * EE + l) * HIDD)
                                        : (kvh  + ((size_t)b * SS + (l - EE)) * HIDD);
            v = *(const float4*)(row + c4);
        }
        uint32_t h0, l0, h1, l1;
        split2(v.x, v.y, h0, l0);
        split2(v.z, v.w, h1, l1);
        int kc = c4 >> 5, cc = c4 & 31, s = cc >> 3, off = cc & 7;
        int r = m & 127, mblk = m >> 7;
        size_t base = ((size_t)(kc * NMB + mblk)) * 4096 + pA(r, s) * 8 + off;
        *(uint2*)(&g_Eh2[base]) = make_uint2(h0, h1);
        *(uint2*)(&g_El2[base]) = make_uint2(l0, l1);
    } else {
        int idx = (bid - PM_BLK - ZP_BLK - ES_BLK) * 256 + tid;
        int n = idx / 192, c4 = (idx % 192) * 4;
        float4 v = *(const float4*)(W + (size_t)n * HIDD + c4);
        uint32_t h0, l0, h1, l1;
        split2(v.x * 64.f, v.y * 64.f, h0, l0);
        split2(v.z * 64.f, v.w * 64.f, h1, l1);
        int kc = c4 >> 5, cc = c4 & 31, s = cc >> 3, off = cc & 7;
        int r = n & 127, nblk = n >> 7;
        size_t base = ((size_t)(kc * NNB + nblk)) * 4096 + pA(r, s) * 8 + off;
        *(uint2*)(&g_Wh2[base]) = make_uint2(h0, h1);
        *(uint2*)(&g_Wl2[base]) = make_uint2(l0, l1);
    }
}

// ---------------- kernel 3: KV projection mma.sync, hi/lo, bulk-copy pipeline ----------------
#define PJ_STAGE 32768
#define PJ_SMEM  (128 + 2 * PJ_STAGE)

__global__ void __launch_bounds__(256) projmma_kernel(const float* __restrict__ bias)
{
    extern __shared__ __align__(128) char pj_sm[];
    const uint32_t sb = smem_u32(pj_sm);
    const uint32_t mb0 = sb, mb1 = sb + 8;
    const uint32_t bufs = sb + 128;
    const int tid = threadIdx.x, w = tid >> 5, lane = tid & 31;
    const int grp = lane >> 2, qc = lane & 3;
    const int wm = w >> 1, wn = w & 1;
    const int n0 = blockIdx.x * 128, m0 = blockIdx.y * 128;
    const int mbi = m0 >> 7, nbi = n0 >> 7;

    if (tid == 0) { MBAR_INIT(mb0, 1); MBAR_INIT(mb1, 1); }
    __syncthreads();
    if (tid == 0) {
#pragma unroll
        for (int kc = 0; kc < 2; ++kc) {
            const uint32_t buf = bufs + kc * PJ_STAGE;
            const uint32_t mb = kc ? mb1 : mb0;
            MBAR_EXPECT(mb, PJ_STAGE);
            bulkcp(buf,         (const char*)g_Eh2 + (((size_t)(kc * NMB + mbi)) << 13), 8192, mb);
            bulkcp(buf + 8192,  (const char*)g_El2 + (((size_t)(kc * NMB + mbi)) << 13), 8192, mb);
            bulkcp(buf + 16384, (const char*)g_Wh2 + (((size_t)(kc * NNB + nbi)) << 13), 8192, mb);
            bulkcp(buf + 24576, (const char*)g_Wl2 + (((size_t)(kc * NNB + nbi)) << 13), 8192, mb);
        }
    }

    float acc[2][8][4];
#pragma unroll
    for (int i = 0; i < 2; ++i)
#pragma unroll
        for (int t = 0; t < 8; ++t)
#pragma unroll
            for (int x = 0; x < 4; ++x) acc[i][t][x] = 0.f;

    const int arow = (lane & 7) + 8 * ((lane >> 3) & 1);
    const int asel = lane >> 4;
    const int bsel = lane >> 3;
    const int brl  = lane & 7;

    for (int kc = 0; kc < NKC; ++kc) {
        MBAR_WAIT((kc & 1) ? mb1 : mb0, (kc >> 1) & 1);
        const uint32_t buf = bufs + (kc & 1) * PJ_STAGE;

        uint32_t ah0[2][4], ah1[2][4], al0[2][4], al1[2][4];
#pragma unroll
        for (int i = 0; i < 2; ++i) {
            const int r = wm * 32 + i * 16 + arow;
            const uint32_t o0 = buf + pA(r, 0 + asel) * 16;
            const uint32_t o1 = buf + pA(r, 2 + asel) * 16;
            ldmx4(o0,        ah0[i]);
            ldmx4(o1,        ah1[i]);
            ldmx4(o0 + 8192, al0[i]);
            ldmx4(o1 + 8192, al1[i]);
        }
#pragma unroll
        for (int t = 0; t < 8; ++t) {
            const int rn = wn * 64 + t * 8 + brl;
            const uint32_t ob = buf + pA(rn, bsel) * 16;
            uint32_t bh[4], bl[4];
            ldmx4(ob + 16384, bh);
            ldmx4(ob + 24576, bl);
#pragma unroll
            for (int i = 0; i < 2; ++i) {
                mma16816(acc[i][t], ah0[i], bh[0], bh[1]);
                mma16816(acc[i][t], ah1[i], bh[2], bh[3]);
                mma16816(acc[i][t], ah0[i], bl[0], bl[1]);
                mma16816(acc[i][t], ah1[i], bl[2], bl[3]);
                mma16816(acc[i][t], al0[i], bh[0], bh[1]);
                mma16816(acc[i][t], al1[i], bh[2], bh[3]);
            }
        }
        __syncthreads();
        if (tid == 0 && kc + 2 < NKC) {
            const int kn = kc + 2;
            const uint32_t buf2 = bufs + (kn & 1) * PJ_STAGE;
            const uint32_t mb = (kn & 1) ? mb1 : mb0;
            MBAR_EXPECT(mb, PJ_STAGE);
            bulkcp(buf2,         (const char*)g_Eh2 + (((size_t)(kn * NMB + mbi)) << 13), 8192, mb);
            bulkcp(buf2 + 8192,  (const char*)g_El2 + (((size_t)(kn * NMB + mbi)) << 13), 8192, mb);
            bulkcp(buf2 + 16384, (const char*)g_Wh2 + (((size_t)(kn * NNB + nbi)) << 13), 8192, mb);
            bulkcp(buf2 + 24576, (const char*)g_Wl2 + (((size_t)(kn * NNB + nbi)) << 13), 8192, mb);
        }
    }

    const float inv64 = 0.015625f;
    const bool isK = (n0 < HIDD);
#pragma unroll
    for (int t = 0; t < 8; ++t) {
        const int n = n0 + wn * 64 + t * 8 + 2 * qc;
        const float b0f = bias[n], b1f = bias[n + 1];
        const int rem = isK ? n : (n - HIDD);
        const int hh = rem >> 6, d = rem & 63;
#pragma unroll
        for (int i = 0; i < 2; ++i) {
            const int mbase = m0 + wm * 32 + i * 16 + grp;
#pragma unroll
            for (int rs = 0; rs < 2; ++rs) {
                const int mm = mbase + rs * 8;
                if (mm >= MTOT) continue;
                const int b = mm / LL, l = mm % LL;
                const int bh = b * NHH + hh;
                const int kt = l >> 7, r = l & 127;
                const float v0 = acc[i][t][2 * rs]     * inv64 + b0f;
                const float v1 = acc[i][t][2 * rs + 1] * inv64 + b1f;
                if (isK) {
                    const int pi = d >> 1;
                    const float si = g_emb[l * 64 + pi], ci = g_emb[l * 64 + 32 + pi];
                    const int s = d >> 3, off = d & 7;
                    *(uint32_t*)(&g_Kt[((size_t)(bh * NT + kt)) * 8192 + pK(r, s) * 8 + off]) =
                        packh2(-v1 * ci, v0 * si);
                } else {
                    const int s = r >> 3, off = r & 7;
                    const size_t tb = ((size_t)(bh * NT + kt)) * 8192;
                    g_Vtt[tb + pV(d, s) * 8 + off]     = __float2half_rn(v0);
                    g_Vtt[tb + pV(d + 1, s) * 8 + off] = __float2half_rn(v1);
                }
            }
        }
    }
}

// ---------------- kernel 4: attention, 128 q-rows / 8 warps / 256 threads ----------------
#define AT_STAGE 32768
#define AT_SMEM  (128 + 2 * AT_STAGE)

__global__ void __launch_bounds__(256) attn_kernel(float* __restrict__ out)
{
    extern __shared__ __align__(128) char at_sm[];
    const uint32_t sb = smem_u32(at_sm);
    const uint32_t mb0 = sb, mb1 = sb + 8;
    const uint32_t bufs = sb + 128;
    const int tid = threadIdx.x, w = tid >> 5, lane = tid & 31;
    const int grp = lane >> 2, qc = lane & 3;
    const int q0 = blockIdx.x * 128, h = blockIdx.y, b = blockIdx.z;
    const int bh = b * NHH + h;
    const int r0 = w * 16 + grp;               // warp covers q-rows q0+w*16 .. +15

    if (tid == 0) { MBAR_INIT(mb0, 1); MBAR_INIT(mb1, 1); }
    __syncthreads();
    if (tid == 0) {
#pragma unroll
        for (int kt = 0; kt < 2; ++kt) {
            const uint32_t buf = bufs + kt * AT_STAGE;
            const uint32_t mb = kt ? mb1 : mb0;
            MBAR_EXPECT(mb, AT_STAGE);
            bulkcp(buf,         (const char*)g_Kt  + (((size_t)(bh * NT + kt)) << 14), 16384, mb);
            bulkcp(buf + 16384, (const char*)g_Vtt + (((size_t)(bh * NT + kt)) << 14), 16384, mb);
        }
    }

    uint32_t qa[4][4];
    {
        const __half* q0p = g_Qf + ((size_t)(bh * SS + q0 + r0)) * HDD;
        const __half* q8p = q0p + 8 * HDD;
#pragma unroll
        for (int kc = 0; kc < 4; ++kc) {
            int d0 = 16 * kc + 2 * qc;
            qa[kc][0] = *(const uint32_t*)(q0p + d0);
            qa[kc][1] = *(const uint32_t*)(q8p + d0);
            qa[kc][2] = *(const uint32_t*)(q0p + d0 + 8);
            qa[kc][3] = *(const uint32_t*)(q8p + d0 + 8);
        }
    }

    const uint4* mp0 = (const uint4*)(g_mask + (size_t)(b * SS + q0 + r0) * MW);
    const uint4* mp1 = (const uint4*)(g_mask + (size_t)(b * SS + q0 + r0 + 8) * MW);

    float O[8][4];
#pragma unroll
    for (int u = 0; u < 8; ++u)
#pragma unroll
        for (int x = 0; x < 4; ++x) O[u][x] = 0.f;
    float ls0 = 0.f, ls1 = 0.f;

    const int lrl = lane & 7;
    const int lsg = lane >> 3;

    for (int kt = 0; kt < NT; ++kt) {
        MBAR_WAIT((kt & 1) ? mb1 : mb0, (kt >> 1) & 1);
        const uint32_t kbuf = bufs + (kt & 1) * AT_STAGE;
        const uint32_t vbuf = kbuf + 16384;

        float s[16][4];
#pragma unroll
        for (int t = 0; t < 16; ++t) {
            s[t][0] = s[t][1] = s[t][2] = s[t][3] = 0.f;
            const int r = 8 * t + lrl;
#pragma unroll
            for (int p = 0; p < 2; ++p) {
                uint32_t bf[4];
                ldmx4(kbuf + pK(r, 4 * p + lsg) * 16, bf);
                mma16816(s[t], qa[2 * p],     bf[0], bf[1]);
                mma16816(s[t], qa[2 * p + 1], bf[2], bf[3]);
            }
        }

        const uint4 mw0 = mp0[kt];
        const uint4 mw1 = mp1[kt];
        uint32_t ph[32];
#pragma unroll
        for (int t = 0; t < 16; ++t) {
            const unsigned w0 = ((const unsigned*)&mw0)[t >> 2];
            const unsigned w1 = ((const unsigned*)&mw1)[t >> 2];
            const int bit = 8 * (t & 3) + 2 * qc;
            float p00 = ((w0 >> bit) & 1u)       ? exp2f(s[t][0]) : 0.f;
            float p01 = ((w0 >> (bit + 1)) & 1u) ? exp2f(s[t][1]) : 0.f;
            float p10 = ((w1 >> bit) & 1u)       ? exp2f(s[t][2]) : 0.f;
            float p11 = ((w1 >> (bit + 1)) & 1u) ? exp2f(s[t][3]) : 0.f;
            ls0 += p00 + p01;
            ls1 += p10 + p11;
            ph[2 * t]     = packh2(p00, p01);
            ph[2 * t + 1] = packh2(p10, p11);
        }

#pragma unroll
        for (int u = 0; u < 8; ++u) {
            const int d = 8 * u + lrl;
#pragma unroll
            for (int p2 = 0; p2 < 4; ++p2) {
                uint32_t bf[4];
                ldmx4(vbuf + pV(d, 4 * p2 + lsg) * 16, bf);
                mma16816(O[u], &ph[8 * p2],     bf[0], bf[1]);
                mma16816(O[u], &ph[8 * p2 + 4], bf[2], bf[3]);
            }
        }
        __syncthreads();
        if (tid == 0 && kt + 2 < NT) {
            const int kn = kt + 2;
            const uint32_t buf2 = bufs + (kn & 1) * AT_STAGE;
            const uint32_t mb = (kn & 1) ? mb1 : mb0;
            MBAR_EXPECT(mb, AT_STAGE);
            bulkcp(buf2,         (const char*)g_Kt  + (((size_t)(bh * NT + kn)) << 14), 16384, mb);
            bulkcp(buf2 + 16384, (const char*)g_Vtt + (((size_t)(bh * NT + kn)) << 14), 16384, mb);
        }
    }

    ls0 += __shfl_xor_sync(0xffffffffu, ls0, 1);
    ls0 += __shfl_xor_sync(0xffffffffu, ls0, 2);
    ls1 += __shfl_xor_sync(0xffffffffu, ls1, 1);
    ls1 += __shfl_xor_sync(0xffffffffu, ls1, 2);
    const float inv0 = 1.f / ls0, inv1 = 1.f / ls1;

    float* o0 = out + ((size_t)(b * SS + q0 + r0)) * HIDD + h * HDD;
    float* o8 = o0 + 8 * HIDD;
#pragma unroll
    for (int u = 0; u < 8; ++u) {
        const int d0 = 8 * u + 2 * qc;
        *(float2*)(o0 + d0) = make_float2(O[u][0] * inv0, O[u][1] * inv0);
        *(float2*)(o8 + d0) = make_float2(O[u][2] * inv1, O[u][3] * inv1);
    }
}

// ---------------- launch ----------------
extern "C" void kernel_launch(void* const* d_in, const int* in_sizes, int n_in,
                              void* d_out, int out_size) {
    const float *qh = 0, *kvh = 0, *embx = 0, *rnd = 0, *Wkv_w = 0, *Wkv_b = 0;
    const float *big[2] = {0, 0};
    int nbig = 0;
    for (int i = 0; i < n_in; ++i) {
        switch (in_sizes[i]) {
            case 3145728: if (nbig < 2) big[nbig++] = (const float*)d_in[i]; break;
            case 12288:   embx  = (const float*)d_in[i]; break;
            case 8388608: rnd   = (const float*)d_in[i]; break;
            case 1179648: Wkv_w = (const float*)d_in[i]; break;
            case 1536:    Wkv_b = (const float*)d_in[i]; break;
            default: break;
        }
    }
    if (nbig == 2) {
        if (in_sizes[0] == 3145728) { qh = big[0]; kvh = big[1]; }
        else                        { kvh = big[0]; qh = big[1]; }
    }
    if (!qh || !kvh || !embx || !rnd || !Wkv_w || !Wkv_b) {
        qh    = (const float*)d_in[0];
        kvh   = (const float*)d_in[1];
        embx  = (const float*)d_in[2];
        rnd   = (const float*)d_in[3];
        Wkv_w = (const float*)d_in[6];
        Wkv_b = (const float*)d_in[7];
    }
    float* out = (float*)d_out;

    prep_kernel<<<PREP_GRID, 256>>>(rnd, kvh, embx, Wkv_w);
    emb_kernel<<<(LL * 32 + 255) / 256, 256>>>();
    qf16_kernel<<<(BB * SS * NHH * 32 + 255) / 256, 256>>>(qh);

    cudaFuncSetAttribute(projmma_kernel, cudaFuncAttributeMaxDynamicSharedMemorySize, PJ_SMEM);
    projmma_kernel<<<dim3(NKV / 128, MPAD / 128), 256, PJ_SMEM>>>(Wkv_b);

    cudaFuncSetAttribute(attn_kernel, cudaFuncAttributeMaxDynamicSharedMemorySize, AT_SMEM);
    attn_kernel<<<dim3(SS / 128, NHH, BB), 256, AT_SMEM>>>(out);
}

// round 16
// speedup vs baseline: 1.1711x; 1.1711x over previous
#include <cuda_runtime.h>
#include <cuda_fp16.h>
#include <math.h>
#include <stdint.h>

#define BB   2
#define SS   2048
#define EE   8
#define LL   2056
#define HIDD 768
#define HDD  64
#define NHH  12
#define MTOT (BB*LL)         // 4112
#define MPAD 4224            // 33 * 128
#define NKV  (2*HIDD)
#define NT   17
#define MW   68
#define NKC  24              // k-chunks of 32
#define NMB  33              // m-blocks of 128
#define NNB  12              // n-blocks of 128
#define NBH  (BB*NHH)

// ---------------- scratch (tiled, pre-swizzled layouts) ----------------
__device__ __align__(16) __half g_Qf[NBH*SS*HDD];                // [bh][s][d], scaled by 0.125*log2(e)
__device__ __align__(16) __half g_Eh2[NKC*NMB*4096];
__device__ __align__(16) __half g_El2[NKC*NMB*4096];
__device__ __align__(16) __half g_Wh2[NKC*NNB*4096];
__device__ __align__(16) __half g_Wl2[NKC*NNB*4096];
__device__ __align__(16) __half g_Kt [NBH*NT*8192];              // per (bh,kt): 128r x 8u tile
__device__ __align__(16) __half g_Vtt[NBH*NT*8192];              // per (bh,kt): 64d x 16u tile
__device__ __align__(16) unsigned g_mask[BB*SS*MW];
__device__ float g_emb[LL*HDD];

// ---------------- swizzled unit positions (unit = 16B = 8 halfs) ----------------
__device__ __forceinline__ int pA(int r, int s) {
    int q = r >> 1, j = s + ((r & 1) << 2);
    return q * 8 + (j ^ (q & 7));
}
__device__ __forceinline__ int pK(int r, int s) { return r * 8 + (s ^ (r & 7)); }
__device__ __forceinline__ int pV(int d, int s) { return d * 16 + (s ^ (d & 7)); }

// ---------------- helpers ----------------
__device__ __forceinline__ uint32_t smem_u32(const void* p) {
    uint32_t a;
    asm("{ .reg .u64 t; cvta.to.shared.u64 t, %1; cvt.u32.u64 %0, t; }" : "=r"(a) : "l"(p));
    return a;
}
__device__ __forceinline__ uint32_t packh2(float lo, float hi) {
    uint32_t r; asm("cvt.rn.f16x2.f32 %0, %1, %2;" : "=r"(r) : "f"(hi), "f"(lo)); return r;
}
__device__ __forceinline__ void mma16816(float* c, const uint32_t* a, uint32_t b0, uint32_t b1) {
    asm volatile("mma.sync.aligned.m16n8k16.row.col.f32.f16.f16.f32 "
        "{%0,%1,%2,%3}, {%4,%5,%6,%7}, {%8,%9}, {%0,%1,%2,%3};"
        : "+f"(c[0]), "+f"(c[1]), "+f"(c[2]), "+f"(c[3])
        : "r"(a[0]), "r"(a[1]), "r"(a[2]), "r"(a[3]), "r"(b0), "r"(b1));
}
__device__ __forceinline__ void ldmx4(uint32_t a, uint32_t* r) {
    asm volatile("ldmatrix.sync.aligned.m8n8.x4.shared.b16 {%0,%1,%2,%3}, [%4];"
        : "=r"(r[0]), "=r"(r[1]), "=r"(r[2]), "=r"(r[3]) : "r"(a));
}
__device__ __forceinline__ void bulkcp(uint32_t dst, const void* src, uint32_t bytes, uint32_t mbar) {
    asm volatile("cp.async.bulk.shared::cluster.global.mbarrier::complete_tx::bytes [%0], [%1], %2, [%3];"
        :: "r"(dst), "l"(src), "r"(bytes), "r"(mbar) : "memory");
}
#define MBAR_INIT(a, c) \
    asm volatile("mbarrier.init.shared.b64 [%0], %1;" :: "r"(a), "r"((uint32_t)(c)) : "memory")
#define MBAR_EXPECT(a, tx) \
    asm volatile("mbarrier.arrive.expect_tx.shared.b64 _, [%0], %1;" :: "r"(a), "r"((uint32_t)(tx)) : "memory")
#define MBAR_WAIT(a, ph) do { \
    uint32_t _m = (a), _p = (uint32_t)(ph), _d; \
    asm volatile("{\n\t.reg .pred p;\n\tmbarrier.try_wait.parity.acquire.cta.shared::cta.b64 p, [%1], %2;\n\tselp.b32 %0, 1, 0, p;\n\t}" \
        : "=r"(_d) : "r"(_m), "r"(_p) : "memory"); \
    if (!_d) { \
        asm volatile("{\n\t.reg .pred P1;\n\tWL_%=:\n\tmbarrier.try_wait.parity.acquire.cta.shared::cta.b64 P1, [%0], %1, 0x989680;\n\t@P1 bra.uni WD_%=;\n\tbra.uni WL_%=;\n\tWD_%=:\n\t}" \
            :: "r"(_m), "r"(_p) : "memory"); \
    } \
} while (0)

// ---------------- kernel 1: Q rope + (0.125*log2e) scale -> fp16 ----------------
#define QSCALE 0.1803368801111204f   // 0.125 * log2(e)
__global__ void qf16_kernel(const float* __restrict__ qh) {
    int idx = blockIdx.x * blockDim.x + threadIdx.x;
    if (idx >= BB * SS * NHH * 32) return;
    int i = idx & 31;
    int t = idx >> 5;
    int h = t % NHH;  t /= NHH;
    int p = t % SS;
    int b = t / SS;
    const float2 x = *(const float2*)(qh + ((size_t)(b * SS + p)) * HIDD + h * HDD + 2 * i);
    float si = g_emb[p * 64 + i];
    float ci = g_emb[p * 64 + 32 + i];
    size_t o = ((size_t)(b * NHH + h) * SS + p) * HDD + 2 * i;
    *(uint32_t*)(&g_Qf[o]) = packh2(-x.y * ci * QSCALE, x.x * si * QSCALE);
}

// ---------------- fused prep: emb + packmask + zeropad + esplit + wsplit ----------------
#define EM_BLK 257
#define PM_BLK 512
#define ZP_BLK 180
#define ES_BLK 3168
#define WS_BLK 1152
#define PREP_GRID (EM_BLK + PM_BLK + ZP_BLK + ES_BLK + WS_BLK)

__device__ __forceinline__ void split2(float a, float b, uint32_t& hw, uint32_t& lw) {
    __half ha = __float2half_rn(a), hb = __float2half_rn(b);
    hw = ((uint32_t)__half_as_ushort(hb) << 16) | __half_as_ushort(ha);
    __half la = __float2half_rn(a - __half2float(ha));
    __half lb = __float2half_rn(b - __half2float(hb));
    lw = ((uint32_t)__half_as_ushort(lb) << 16) | __half_as_ushort(la);
}

__global__ void prep_kernel(const float* __restrict__ rnd, const float* __restrict__ kvh,
                            const float* __restrict__ embx, const float* __restrict__ W) {
    const int bid = blockIdx.x, tid = threadIdx.x;
    if (bid < EM_BLK) {
        int idx = bid * 256 + tid;           // LL*32 = 65792 = 257*256 exact
        int p = idx >> 5, j = idx & 31;
        float divf = (float)exp(-(double)(2 * j) * (9.210340371976184 / 64.0));
        float angf = (float)p * divf;
        double ang = (double)angf;
        g_emb[p * 64 + 2 * j]     = (float)sin(ang);
        g_emb[p * 64 + 2 * j + 1] = (float)cos(ang);
    } else if (bid < EM_BLK + PM_BLK) {
        int wid_g = (bid - EM_BLK) * 8 + (tid >> 5);
        int lane = tid & 31;
        int b = wid_g >> 11, q = wid_g & 2047;
        const float* rrow = rnd + ((size_t)(b * SS + q)) * SS;
        unsigned* mrow = g_mask + (size_t)wid_g * MW;
        for (int w = 0; w < MW; ++w) {
            int j = w * 32 + lane;
            bool ok;
            if (j < EE) ok = true;
            else {
                int jj = j - EE;
                ok = (jj < SS) ? ((rrow[jj] >= 0.1f) & (jj != q)) : false;
            }
            unsigned bal = __ballot_sync(0xffffffffu, ok);
            if (lane == 0) mrow[w] = bal;
        }
    } else if (bid < EM_BLK + PM_BLK + ZP_BLK) {
        int idx = (bid - EM_BLK - PM_BLK) * 256 + tid;   // 0 .. 46079
        const uint4 z = make_uint4(0, 0, 0, 0);
        if (idx < 23040) {                       // K pad: tile kt=16, rows 8..127
            int s = idx & 7;
            int t2 = idx >> 3;
            int r = 8 + t2 % 120;
            int bh = t2 / 120;
            *(uint4*)(&g_Kt[((size_t)(bh * NT + 16)) * 8192 + pK(r, s) * 8]) = z;
        } else {                                 // V pad: tile kt=16, units 1..15
            int i2 = idx - 23040;
            int s = 1 + i2 % 15;
            int t2 = i2 / 15;
            int d = t2 & 63;
            int bh = t2 >> 6;
            *(uint4*)(&g_Vtt[((size_t)(bh * NT + 16)) * 8192 + pV(d, s) * 8]) = z;
        }
    } else if (bid < EM_BLK + PM_BLK + ZP_BLK + ES_BLK) {
        int idx = (bid - EM_BLK - PM_BLK - ZP_BLK) * 256 + tid;
        int m = idx / 192, c4 = (idx % 192) * 4;
        float4 v = make_float4(0.f, 0.f, 0.f, 0.f);
        if (m < MTOT) {
            int b = m / LL, l = m % LL;
            const float* row = (l < EE) ? (embx + ((size_t)b * EE + l) * HIDD)
                                        : (kvh  + ((size_t)b * SS + (l - EE)) * HIDD);
            v = *(const float4*)(row + c4);
        }
        uint32_t h0, l0, h1, l1;
        split2(v.x, v.y, h0, l0);
        split2(v.z, v.w, h1, l1);
        int kc = c4 >> 5, cc = c4 & 31, s = cc >> 3, off = cc & 7;
        int r = m & 127, mblk = m >> 7;
        size_t base = ((size_t)(kc * NMB + mblk)) * 4096 + pA(r, s) * 8 + off;
        *(uint2*)(&g_Eh2[base]) = make_uint2(h0, h1);
        *(uint2*)(&g_El2[base]) = make_uint2(l0, l1);
    } else {
        int idx = (bid - EM_BLK - PM_BLK - ZP_BLK - ES_BLK) * 256 + tid;
        int n = idx / 192, c4 = (idx % 192) * 4;
        float4 v = *(const float4*)(W + (size_t)n * HIDD + c4);
        uint32_t h0, l0, h1, l1;
        split2(v.x * 64.f, v.y * 64.f, h0, l0);
        split2(v.z * 64.f, v.w * 64.f, h1, l1);
        int kc = c4 >> 5, cc = c4 & 31, s = cc >> 3, off = cc & 7;
        int r = n & 127, nblk = n >> 7;
        size_t base = ((size_t)(kc * NNB + nblk)) * 4096 + pA(r, s) * 8 + off;
        *(uint2*)(&g_Wh2[base]) = make_uint2(h0, h1);
        *(uint2*)(&g_Wl2[base]) = make_uint2(l0, l1);
    }
}

// ---------------- kernel 3: KV projection mma.sync, hi/lo, bulk-copy pipeline ----------------
#define PJ_STAGE 32768
#define PJ_SMEM  (128 + 2 * PJ_STAGE)

__global__ void __launch_bounds__(256) projmma_kernel(const float* __restrict__ bias)
{
    extern __shared__ __align__(128) char pj_sm[];
    const uint32_t sb = smem_u32(pj_sm);
    const uint32_t mb0 = sb, mb1 = sb + 8;
    const uint32_t bufs = sb + 128;
    const int tid = threadIdx.x, w = tid >> 5, lane = tid & 31;
    const int grp = lane >> 2, qc = lane & 3;
    const int wm = w >> 1, wn = w & 1;
    const int n0 = blockIdx.x * 128, m0 = blockIdx.y * 128;
    const int mbi = m0 >> 7, nbi = n0 >> 7;

    if (tid == 0) { MBAR_INIT(mb0, 1); MBAR_INIT(mb1, 1); }
    __syncthreads();
    if (tid == 0) {
#pragma unroll
        for (int kc = 0; kc < 2; ++kc) {
            const uint32_t buf = bufs + kc * PJ_STAGE;
            const uint32_t mb = kc ? mb1 : mb0;
            MBAR_EXPECT(mb, PJ_STAGE);
            bulkcp(buf,         (const char*)g_Eh2 + (((size_t)(kc * NMB + mbi)) << 13), 8192, mb);
            bulkcp(buf + 8192,  (const char*)g_El2 + (((size_t)(kc * NMB + mbi)) << 13), 8192, mb);
            bulkcp(buf + 16384, (const char*)g_Wh2 + (((size_t)(kc * NNB + nbi)) << 13), 8192, mb);
            bulkcp(buf + 24576, (const char*)g_Wl2 + (((size_t)(kc * NNB + nbi)) << 13), 8192, mb);
        }
    }

    float acc[2][8][4];
#pragma unroll
    for (int i = 0; i < 2; ++i)
#pragma unroll
        for (int t = 0; t < 8; ++t)
#pragma unroll
            for (int x = 0; x < 4; ++x) acc[i][t][x] = 0.f;

    const int arow = (lane & 7) + 8 * ((lane >> 3) & 1);
    const int asel = lane >> 4;
    const int bsel = lane >> 3;
    const int brl  = lane & 7;

    for (int kc = 0; kc < NKC; ++kc) {
        MBAR_WAIT((kc & 1) ? mb1 : mb0, (kc >> 1) & 1);
        const uint32_t buf = bufs + (kc & 1) * PJ_STAGE;

        uint32_t ah0[2][4], ah1[2][4], al0[2][4], al1[2][4];
#pragma unroll
        for (int i = 0; i < 2; ++i) {
            const int r = wm * 32 + i * 16 + arow;
            const uint32_t o0 = buf + pA(r, 0 + asel) * 16;
            const uint32_t o1 = buf + pA(r, 2 + asel) * 16;
            ldmx4(o0,        ah0[i]);
            ldmx4(o1,        ah1[i]);
            ldmx4(o0 + 8192, al0[i]);
            ldmx4(o1 + 8192, al1[i]);
        }
#pragma unroll
        for (int t = 0; t < 8; ++t) {
            const int rn = wn * 64 + t * 8 + brl;
            const uint32_t ob = buf + pA(rn, bsel) * 16;
            uint32_t bh[4], bl[4];
            ldmx4(ob + 16384, bh);
            ldmx4(ob + 24576, bl);
#pragma unroll
            for (int i = 0; i < 2; ++i) {
                mma16816(acc[i][t], ah0[i], bh[0], bh[1]);
                mma16816(acc[i][t], ah1[i], bh[2], bh[3]);
                mma16816(acc[i][t], ah0[i], bl[0], bl[1]);
                mma16816(acc[i][t], ah1[i], bl[2], bl[3]);
                mma16816(acc[i][t], al0[i], bh[0], bh[1]);
                mma16816(acc[i][t], al1[i], bh[2], bh[3]);
            }
        }
        __syncthreads();
        if (tid == 0 && kc + 2 < NKC) {
            const int kn = kc + 2;
            const uint32_t buf2 = bufs + (kn & 1) * PJ_STAGE;
            const uint32_t mb = (kn & 1) ? mb1 : mb0;
            MBAR_EXPECT(mb, PJ_STAGE);
            bulkcp(buf2,         (const char*)g_Eh2 + (((size_t)(kn * NMB + mbi)) << 13), 8192, mb);
            bulkcp(buf2 + 8192,  (const char*)g_El2 + (((size_t)(kn * NMB + mbi)) << 13), 8192, mb);
            bulkcp(buf2 + 16384, (const char*)g_Wh2 + (((size_t)(kn * NNB + nbi)) << 13), 8192, mb);
            bulkcp(buf2 + 24576, (const char*)g_Wl2 + (((size_t)(kn * NNB + nbi)) << 13), 8192, mb);
        }
    }

    const float inv64 = 0.015625f;
    const bool isK = (n0 < HIDD);
#pragma unroll
    for (int t = 0; t < 8; ++t) {
        const int n = n0 + wn * 64 + t * 8 + 2 * qc;
        const float b0f = bias[n], b1f = bias[n + 1];
        const int rem = isK ? n : (n - HIDD);
        const int hh = rem >> 6, d = rem & 63;
#pragma unroll
        for (int i = 0; i < 2; ++i) {
            const int mbase = m0 + wm * 32 + i * 16 + grp;
#pragma unroll
            for (int rs = 0; rs < 2; ++rs) {
                const int mm = mbase + rs * 8;
                if (mm >= MTOT) continue;
                const int b = mm / LL, l = mm % LL;
                const int bh = b * NHH + hh;
                const int kt = l >> 7, r = l & 127;
                const float v0 = acc[i][t][2 * rs]     * inv64 + b0f;
                const float v1 = acc[i][t][2 * rs + 1] * inv64 + b1f;
                if (isK) {
                    const int pi = d >> 1;
                    const float si = g_emb[l * 64 + pi], ci = g_emb[l * 64 + 32 + pi];
                    const int s = d >> 3, off = d & 7;
                    *(uint32_t*)(&g_Kt[((size_t)(bh * NT + kt)) * 8192 + pK(r, s) * 8 + off]) =
                        packh2(-v1 * ci, v0 * si);
                } else {
                    const int s = r >> 3, off = r & 7;
                    const size_t tb = ((size_t)(bh * NT + kt)) * 8192;
                    g_Vtt[tb + pV(d, s) * 8 + off]     = __float2half_rn(v0);
                    g_Vtt[tb + pV(d + 1, s) * 8 + off] = __float2half_rn(v1);
                }
            }
        }
    }
}

// ---------------- kernel 4: attention, 64 q-rows / 4 warps, split K/V mbarriers ----------------
#define AT_STAGE 32768
#define AT_SMEM  (128 + 2 * AT_STAGE)

__global__ void __launch_bounds__(128) attn_kernel(float* __restrict__ out)
{
    extern __shared__ __align__(128) char at_sm[];
    const uint32_t sb = smem_u32(at_sm);
    // mbarriers: [stage][K/V] : sb+0 K0, sb+8 V0, sb+16 K1, sb+24 V1
    const uint32_t bufs = sb + 128;
    const int tid = threadIdx.x, w = tid >> 5, lane = tid & 31;
    const int grp = lane >> 2, qc = lane & 3;
    const int q0 = blockIdx.x * 64, h = blockIdx.y, b = blockIdx.z;
    const int bh = b * NHH + h;
    const int r0 = w * 16 + grp;

    if (tid == 0) {
        MBAR_INIT(sb + 0, 1);  MBAR_INIT(sb + 8, 1);
        MBAR_INIT(sb + 16, 1); MBAR_INIT(sb + 24, 1);
    }
    __syncthreads();
    if (tid == 0) {
#pragma unroll
        for (int kt = 0; kt < 2; ++kt) {
            const uint32_t buf = bufs + kt * AT_STAGE;
            const uint32_t mbK = sb + kt * 16, mbV = mbK + 8;
            MBAR_EXPECT(mbK, 16384);
            bulkcp(buf,         (const char*)g_Kt  + (((size_t)(bh * NT + kt)) << 14), 16384, mbK);
            MBAR_EXPECT(mbV, 16384);
            bulkcp(buf + 16384, (const char*)g_Vtt + (((size_t)(bh * NT + kt)) << 14), 16384, mbV);
        }
    }

    uint32_t qa[4][4];
    {
        const __half* q0p = g_Qf + ((size_t)(bh * SS + q0 + r0)) * HDD;
        const __half* q8p = q0p + 8 * HDD;
#pragma unroll
        for (int kc = 0; kc < 4; ++kc) {
            int d0 = 16 * kc + 2 * qc;
            qa[kc][0] = *(const uint32_t*)(q0p + d0);
            qa[kc][1] = *(const uint32_t*)(q8p + d0);
            qa[kc][2] = *(const uint32_t*)(q0p + d0 + 8);
            qa[kc][3] = *(const uint32_t*)(q8p + d0 + 8);
        }
    }

    const uint4* mp0 = (const uint4*)(g_mask + (size_t)(b * SS + q0 + r0) * MW);
    const uint4* mp1 = (const uint4*)(g_mask + (size_t)(b * SS + q0 + r0 + 8) * MW);

    float O[8][4];
#pragma unroll
    for (int u = 0; u < 8; ++u)
#pragma unroll
        for (int x = 0; x < 4; ++x) O[u][x] = 0.f;
    float ls0 = 0.f, ls1 = 0.f;

    const int lrl = lane & 7;
    const int lsg = lane >> 3;

    for (int kt = 0; kt < NT; ++kt) {
        const uint32_t mbK = sb + (kt & 1) * 16, mbV = mbK + 8;
        const uint32_t ph2 = (kt >> 1) & 1;
        MBAR_WAIT(mbK, ph2);
        const uint32_t kbuf = bufs + (kt & 1) * AT_STAGE;
        const uint32_t vbuf = kbuf + 16384;

        float s[16][4];
#pragma unroll
        for (int t = 0; t < 16; ++t) {
            s[t][0] = s[t][1] = s[t][2] = s[t][3] = 0.f;
            const int r = 8 * t + lrl;
#pragma unroll
            for (int p = 0; p < 2; ++p) {
                uint32_t bf[4];
                ldmx4(kbuf + pK(r, 4 * p + lsg) * 16, bf);
                mma16816(s[t], qa[2 * p],     bf[0], bf[1]);
                mma16816(s[t], qa[2 * p + 1], bf[2], bf[3]);
            }
        }

        const uint4 mw0 = mp0[kt];
        const uint4 mw1 = mp1[kt];
        uint32_t ph[32];
#pragma unroll
        for (int t = 0; t < 16; ++t) {
            const unsigned w0 = ((const unsigned*)&mw0)[t >> 2];
            const unsigned w1 = ((const unsigned*)&mw1)[t >> 2];
            const int bit = 8 * (t & 3) + 2 * qc;
            float p00 = ((w0 >> bit) & 1u)       ? exp2f(s[t][0]) : 0.f;
            float p01 = ((w0 >> (bit + 1)) & 1u) ? exp2f(s[t][1]) : 0.f;
            float p10 = ((w1 >> bit) & 1u)       ? exp2f(s[t][2]) : 0.f;
            float p11 = ((w1 >> (bit + 1)) & 1u) ? exp2f(s[t][3]) : 0.f;
            ls0 += p00 + p01;
            ls1 += p10 + p11;
            ph[2 * t]     = packh2(p00, p01);
            ph[2 * t + 1] = packh2(p10, p11);
        }

        MBAR_WAIT(mbV, ph2);
#pragma unroll
        for (int u = 0; u < 8; ++u) {
            const int d = 8 * u + lrl;
#pragma unroll
            for (int p2 = 0; p2 < 4; ++p2) {
                uint32_t bf[4];
                ldmx4(vbuf + pV(d, 4 * p2 + lsg) * 16, bf);
                mma16816(O[u], &ph[8 * p2],     bf[0], bf[1]);
                mma16816(O[u], &ph[8 * p2 + 4], bf[2], bf[3]);
            }
        }
        __syncthreads();
        if (tid == 0 && kt + 2 < NT) {
            const int kn = kt + 2;
            const uint32_t buf2 = bufs + (kn & 1) * AT_STAGE;
            const uint32_t mbK2 = sb + (kn & 1) * 16, mbV2 = mbK2 + 8;
            MBAR_EXPECT(mbK2, 16384);
            bulkcp(buf2,         (const char*)g_Kt  + (((size_t)(bh * NT + kn)) << 14), 16384, mbK2);
            MBAR_EXPECT(mbV2, 16384);
            bulkcp(buf2 + 16384, (const char*)g_Vtt + (((size_t)(bh * NT + kn)) << 14), 16384, mbV2);
        }
    }

    ls0 += __shfl_xor_sync(0xffffffffu, ls0, 1);
    ls0 += __shfl_xor_sync(0xffffffffu, ls0, 2);
    ls1 += __shfl_xor_sync(0xffffffffu, ls1, 1);
    ls1 += __shfl_xor_sync(0xffffffffu, ls1, 2);
    const float inv0 = 1.f / ls0, inv1 = 1.f / ls1;

    float* o0 = out + ((size_t)(b * SS + q0 + r0)) * HIDD + h * HDD;
    float* o8 = o0 + 8 * HIDD;
#pragma unroll
    for (int u = 0; u < 8; ++u) {
        const int d0 = 8 * u + 2 * qc;
        *(float2*)(o0 + d0) = make_float2(O[u][0] * inv0, O[u][1] * inv0);
        *(float2*)(o8 + d0) = make_float2(O[u][2] * inv1, O[u][3] * inv1);
    }
}

// ---------------- launch ----------------
extern "C" void kernel_launch(void* const* d_in, const int* in_sizes, int n_in,
                              void* d_out, int out_size) {
    const float *qh = 0, *kvh = 0, *embx = 0, *rnd = 0, *Wkv_w = 0, *Wkv_b = 0;
    const float *big[2] = {0, 0};
    int nbig = 0;
    for (int i = 0; i < n_in; ++i) {
        switch (in_sizes[i]) {
            case 3145728: if (nbig < 2) big[nbig++] = (const float*)d_in[i]; break;
            case 12288:   embx  = (const float*)d_in[i]; break;
            case 8388608: rnd   = (const float*)d_in[i]; break;
            case 1179648: Wkv_w = (const float*)d_in[i]; break;
            case 1536:    Wkv_b = (const float*)d_in[i]; break;
            default: break;
        }
    }
    if (nbig == 2) {
        if (in_sizes[0] == 3145728) { qh = big[0]; kvh = big[1]; }
        else                        { kvh = big[0]; qh = big[1]; }
    }
    if (!qh || !kvh || !embx || !rnd || !Wkv_w || !Wkv_b) {
        qh    = (const float*)d_in[0];
        kvh   = (const float*)d_in[1];
        embx  = (const float*)d_in[2];
        rnd   = (const float*)d_in[3];
        Wkv_w = (const float*)d_in[6];
        Wkv_b = (const float*)d_in[7];
    }
    float* out = (float*)d_out;

    prep_kernel<<<PREP_GRID, 256>>>(rnd, kvh, embx, Wkv_w);
    qf16_kernel<<<(BB * SS * NHH * 32 + 255) / 256, 256>>>(qh);

    cudaFuncSetAttribute(projmma_kernel, cudaFuncAttributeMaxDynamicSharedMemorySize, PJ_SMEM);
    projmma_kernel<<<dim3(NKV / 128, MPAD / 128), 256, PJ_SMEM>>>(Wkv_b);

    cudaFuncSetAttribute(attn_kernel, cudaFuncAttributeMaxDynamicSharedMemorySize, AT_SMEM);
    attn_kernel<<<dim3(SS / 64, NHH, BB), 128, AT_SMEM>>>(out);
}